// round 4
// baseline (speedup 1.0000x reference)
#include <cuda_runtime.h>

// Problem dims (fixed by reference)
#define NB 8
#define NP 64
#define NS 512
#define ND 1024
#define NL 64

#define BPD (NB * NP)   // 512 predicate rows total
#define BSD (NB * NS)   // 4096 span rows total

// ---------------- scratch layout (floats) ----------------
// pred   : [512, 1024]
// hidden : [4096, 1024]  (reused for p-hidden then a-hidden)
// pscore : [512]
// ascore : [4096]
// pred2  : [512, 64]
// span2  : [4096, 64]
// U      : [512, 64, 1024]
#define OFF_PRED 0
#define SZ_PRED  (BPD * ND)                       // 524288
#define OFF_HID  (OFF_PRED + SZ_PRED)
#define SZ_HID   (BSD * ND)                       // 4194304
#define OFF_PSC  (OFF_HID + SZ_HID)
#define SZ_PSC   (BPD)                            // 512
#define OFF_ASC  (OFF_PSC + SZ_PSC)
#define SZ_ASC   (BSD)                            // 4096
#define OFF_P2   (OFF_ASC + SZ_ASC)
#define SZ_P2    (BPD * NL)                       // 32768
#define OFF_S2   (OFF_P2 + SZ_P2)
#define SZ_S2    (BSD * NL)                       // 262144
#define OFF_U    (OFF_S2 + SZ_S2)
#define SZ_U     ((size_t)BPD * NL * ND)          // 33554432
#define SCRATCH_FLOATS (OFF_U + SZ_U)             // 38572544 floats ~ 154 MB

__device__ float g_scratch[SCRATCH_FLOATS];

// ---------------- gather predicate rows ----------------
__global__ __launch_bounds__(256) void k_gather(const float* __restrict__ span,
                                                const int* __restrict__ preds,
                                                float* __restrict__ pred_out) {
    int bp = blockIdx.x;                 // 0..511
    int b = bp / NP;
    int s = preds[bp];
    const float4* src = (const float4*)(span + ((size_t)b * NS + s) * ND);
    float4* dst = (float4*)(pred_out + (size_t)bp * ND);
    dst[threadIdx.x] = src[threadIdx.x]; // 256 * float4 = 1024 floats
}

// ---------------- NT GEMM 128x128x16 + bias + relu ----------------
// C[m, j] = relu( sum_d A[m,d] * Bw[j,d] + bias[j] ),  K = N = 1024
__global__ __launch_bounds__(256) void k_gemm_nt_relu(
    const float* __restrict__ A, const float* __restrict__ Bw,
    const float* __restrict__ bias, float* __restrict__ C)
{
    __shared__ float As[16][128];
    __shared__ float Bs[16][128];
    const int tid = threadIdx.x;
    const int tx = tid & 15, ty = tid >> 4;
    const int rowBase = blockIdx.y * 128;
    const int colBase = blockIdx.x * 128;
    const int lr = tid >> 2;            // 0..63
    const int lc = (tid & 3) << 2;      // 0,4,8,12
    const float* Ap = A + (size_t)(rowBase + lr) * ND + lc;
    const float* Bp = Bw + (size_t)(colBase + lr) * ND + lc;

    float acc[8][8];
#pragma unroll
    for (int i = 0; i < 8; i++)
#pragma unroll
        for (int j = 0; j < 8; j++) acc[i][j] = 0.f;

    for (int k0 = 0; k0 < ND; k0 += 16) {
#pragma unroll
        for (int h = 0; h < 2; h++) {
            float4 av = *(const float4*)(Ap + (size_t)h * 64 * ND + k0);
            float4 bv = *(const float4*)(Bp + (size_t)h * 64 * ND + k0);
            As[lc + 0][lr + h * 64] = av.x;
            As[lc + 1][lr + h * 64] = av.y;
            As[lc + 2][lr + h * 64] = av.z;
            As[lc + 3][lr + h * 64] = av.w;
            Bs[lc + 0][lr + h * 64] = bv.x;
            Bs[lc + 1][lr + h * 64] = bv.y;
            Bs[lc + 2][lr + h * 64] = bv.z;
            Bs[lc + 3][lr + h * 64] = bv.w;
        }
        __syncthreads();
#pragma unroll
        for (int k = 0; k < 16; k++) {
            float4 a0 = *(const float4*)&As[k][ty * 8];
            float4 a1 = *(const float4*)&As[k][ty * 8 + 4];
            float4 b0 = *(const float4*)&Bs[k][tx * 8];
            float4 b1 = *(const float4*)&Bs[k][tx * 8 + 4];
            float a[8] = {a0.x, a0.y, a0.z, a0.w, a1.x, a1.y, a1.z, a1.w};
            float bb[8] = {b0.x, b0.y, b0.z, b0.w, b1.x, b1.y, b1.z, b1.w};
#pragma unroll
            for (int i = 0; i < 8; i++)
#pragma unroll
                for (int j = 0; j < 8; j++)
                    acc[i][j] = fmaf(a[i], bb[j], acc[i][j]);
        }
        __syncthreads();
    }
#pragma unroll
    for (int i = 0; i < 8; i++) {
        int row = rowBase + ty * 8 + i;
        float* Cp = C + (size_t)row * ND + colBase + tx * 8;
#pragma unroll
        for (int j = 0; j < 8; j++)
            Cp[j] = fmaxf(acc[i][j] + bias[colBase + tx * 8 + j], 0.f);
    }
}

// ---------------- row dot: score[r] = H[r,:] . w ----------------
__global__ __launch_bounds__(256) void k_rowdot(const float* __restrict__ H,
                                                const float* __restrict__ w,
                                                float* __restrict__ score) {
    int r = blockIdx.x;
    const float* Hp = H + (size_t)r * ND;
    float s = 0.f;
    for (int j = threadIdx.x; j < ND; j += 256) s = fmaf(Hp[j], w[j], s);
    __shared__ float red[256];
    red[threadIdx.x] = s;
    __syncthreads();
    for (int o = 128; o > 0; o >>= 1) {
        if (threadIdx.x < o) red[threadIdx.x] += red[threadIdx.x + o];
        __syncthreads();
    }
    if (threadIdx.x == 0) score[r] = red[0];
}

// ---------------- NN GEMM M x 64, K=1024 (pred2 / span2) ----------------
// C[m,l] = sum_d A[m,d] * Bw[d,l],  Bw row-major [1024, 64]
__global__ __launch_bounds__(256) void k_gemm_nn64(
    const float* __restrict__ A, const float* __restrict__ Bw,
    float* __restrict__ C)
{
    __shared__ float As[16][64];
    __shared__ float Bs[16][64];
    const int tid = threadIdx.x;
    const int tx = tid & 15, ty = tid >> 4;
    const int rowBase = blockIdx.y * 64;
    const int alr = tid >> 2;            // 0..63
    const int alc = (tid & 3) << 2;      // 0..12
    const float* Ap = A + (size_t)(rowBase + alr) * ND + alc;
    const int blr = tid >> 4;            // 0..15
    const int blc = (tid & 15) << 2;     // 0..60
    const float* Bp = Bw + (size_t)blr * NL + blc;

    float acc[4][4];
#pragma unroll
    for (int i = 0; i < 4; i++)
#pragma unroll
        for (int j = 0; j < 4; j++) acc[i][j] = 0.f;

    for (int k0 = 0; k0 < ND; k0 += 16) {
        float4 av = *(const float4*)(Ap + k0);
        As[alc + 0][alr] = av.x;
        As[alc + 1][alr] = av.y;
        As[alc + 2][alr] = av.z;
        As[alc + 3][alr] = av.w;
        float4 bv = *(const float4*)(Bp + (size_t)k0 * NL);
        *(float4*)&Bs[blr][blc] = bv;
        __syncthreads();
#pragma unroll
        for (int k = 0; k < 16; k++) {
            float4 a4 = *(const float4*)&As[k][ty * 4];
            float4 b4 = *(const float4*)&Bs[k][tx * 4];
            float a[4] = {a4.x, a4.y, a4.z, a4.w};
            float bb[4] = {b4.x, b4.y, b4.z, b4.w};
#pragma unroll
            for (int i = 0; i < 4; i++)
#pragma unroll
                for (int j = 0; j < 4; j++)
                    acc[i][j] = fmaf(a[i], bb[j], acc[i][j]);
        }
        __syncthreads();
    }
#pragma unroll
    for (int i = 0; i < 4; i++) {
        int row = rowBase + ty * 4 + i;
        *(float4*)(C + (size_t)row * NL + tx * 4) =
            make_float4(acc[i][0], acc[i][1], acc[i][2], acc[i][3]);
    }
}

// ---------------- Stage 1: U[bp, l, e] = sum_d pred[bp,d] * W1[l,d,e] ----------------
// Batched NN GEMM (z = label), 128x128x16 tiles, strided epilogue write.
__global__ __launch_bounds__(256) void k_gemm_u(
    const float* __restrict__ A, const float* __restrict__ W1,
    float* __restrict__ U)
{
    const int l = blockIdx.z;
    const float* Bw = W1 + (size_t)l * ND * ND;
    __shared__ float As[16][128];
    __shared__ float Bs[16][128];
    const int tid = threadIdx.x;
    const int tx = tid & 15, ty = tid >> 4;
    const int rowBase = blockIdx.y * 128;
    const int colBase = blockIdx.x * 128;
    const int alr = tid >> 2;
    const int alc = (tid & 3) << 2;
    const float* Ap = A + (size_t)(rowBase + alr) * ND + alc;
    const int blr = tid >> 5;            // 0..7
    const int blc = (tid & 31) << 2;     // 0..124
    const float* Bp = Bw + (size_t)blr * ND + colBase + blc;

    float acc[8][8];
#pragma unroll
    for (int i = 0; i < 8; i++)
#pragma unroll
        for (int j = 0; j < 8; j++) acc[i][j] = 0.f;

    for (int k0 = 0; k0 < ND; k0 += 16) {
#pragma unroll
        for (int h = 0; h < 2; h++) {
            float4 av = *(const float4*)(Ap + (size_t)h * 64 * ND + k0);
            As[alc + 0][alr + h * 64] = av.x;
            As[alc + 1][alr + h * 64] = av.y;
            As[alc + 2][alr + h * 64] = av.z;
            As[alc + 3][alr + h * 64] = av.w;
            float4 bv = *(const float4*)(Bp + (size_t)(k0 + h * 8) * ND);
            *(float4*)&Bs[blr + h * 8][blc] = bv;
        }
        __syncthreads();
#pragma unroll
        for (int k = 0; k < 16; k++) {
            float4 a0 = *(const float4*)&As[k][ty * 8];
            float4 a1 = *(const float4*)&As[k][ty * 8 + 4];
            float4 b0 = *(const float4*)&Bs[k][tx * 8];
            float4 b1 = *(const float4*)&Bs[k][tx * 8 + 4];
            float a[8] = {a0.x, a0.y, a0.z, a0.w, a1.x, a1.y, a1.z, a1.w};
            float bb[8] = {b0.x, b0.y, b0.z, b0.w, b1.x, b1.y, b1.z, b1.w};
#pragma unroll
            for (int i = 0; i < 8; i++)
#pragma unroll
                for (int j = 0; j < 8; j++)
                    acc[i][j] = fmaf(a[i], bb[j], acc[i][j]);
        }
        __syncthreads();
    }
#pragma unroll
    for (int i = 0; i < 8; i++) {
        int row = rowBase + ty * 8 + i;
        float* Up = U + (size_t)row * (NL * ND) + (size_t)l * ND + colBase + tx * 8;
        *(float4*)Up = make_float4(acc[i][0], acc[i][1], acc[i][2], acc[i][3]);
        *(float4*)(Up + 4) = make_float4(acc[i][4], acc[i][5], acc[i][6], acc[i][7]);
    }
}

// ---------------- Stage 2 + epilogue ----------------
// out[bp, s, l] = sum_e span[b,s,e]*U[bp,l,e] + pred2[bp,l] + span2[b,s,l]
//               + bias[l] + pscore[bp] + ascore[b,s];  l == 63 -> 0
__global__ __launch_bounds__(256) void k_final(
    const float* __restrict__ span, const float* __restrict__ U,
    const float* __restrict__ pred2, const float* __restrict__ span2,
    const float* __restrict__ pscore, const float* __restrict__ ascore,
    const float* __restrict__ bias, float* __restrict__ out)
{
    const int bp = blockIdx.z;           // 0..511
    const int b = bp >> 6;               // / NP
    __shared__ float As[16][64];         // span rows s
    __shared__ float Bs[16][64];         // U rows l (NT)
    const int tid = threadIdx.x;
    const int tx = tid & 15, ty = tid >> 4;
    const int sBase = blockIdx.y * 64;
    const int lr = tid >> 2;             // 0..63
    const int lc = (tid & 3) << 2;
    const float* Ap = span + ((size_t)b * NS + sBase + lr) * ND + lc;
    const float* Bp = U + (size_t)bp * (NL * ND) + (size_t)lr * ND + lc;

    float acc[4][4];
#pragma unroll
    for (int i = 0; i < 4; i++)
#pragma unroll
        for (int j = 0; j < 4; j++) acc[i][j] = 0.f;

    for (int k0 = 0; k0 < ND; k0 += 16) {
        float4 av = *(const float4*)(Ap + k0);
        As[lc + 0][lr] = av.x;
        As[lc + 1][lr] = av.y;
        As[lc + 2][lr] = av.z;
        As[lc + 3][lr] = av.w;
        float4 bv = *(const float4*)(Bp + k0);
        Bs[lc + 0][lr] = bv.x;
        Bs[lc + 1][lr] = bv.y;
        Bs[lc + 2][lr] = bv.z;
        Bs[lc + 3][lr] = bv.w;
        __syncthreads();
#pragma unroll
        for (int k = 0; k < 16; k++) {
            float4 a4 = *(const float4*)&As[k][ty * 4];
            float4 b4 = *(const float4*)&Bs[k][tx * 4];
            float a[4] = {a4.x, a4.y, a4.z, a4.w};
            float bb[4] = {b4.x, b4.y, b4.z, b4.w};
#pragma unroll
            for (int i = 0; i < 4; i++)
#pragma unroll
                for (int j = 0; j < 4; j++)
                    acc[i][j] = fmaf(a[i], bb[j], acc[i][j]);
        }
        __syncthreads();
    }

    const float ps = pscore[bp];
    const int l0 = tx * 4;
    const float* p2 = pred2 + (size_t)bp * NL + l0;
    const float* bi = bias + l0;
#pragma unroll
    for (int i = 0; i < 4; i++) {
        int s = sBase + ty * 4 + i;
        float add_s = ascore[b * NS + s] + ps;
        const float* s2 = span2 + ((size_t)b * NS + s) * NL + l0;
        float4 v;
        v.x = acc[i][0] + p2[0] + s2[0] + bi[0] + add_s;
        v.y = acc[i][1] + p2[1] + s2[1] + bi[1] + add_s;
        v.z = acc[i][2] + p2[2] + s2[2] + bi[2] + add_s;
        v.w = acc[i][3] + p2[3] + s2[3] + bi[3] + add_s;
        if (l0 + 3 == NL - 1) v.w = 0.f;  // null-label column
        *(float4*)(out + ((size_t)bp * NS + s) * NL + l0) = v;
    }
}

// ---------------- labels cast + tail zero ----------------
__global__ void k_labels(const int* __restrict__ lab, float* __restrict__ out, int n) {
    int i = blockIdx.x * blockDim.x + threadIdx.x;
    if (i < n) out[i] = (float)lab[i];
}
__global__ void k_zero(float* __restrict__ out, int n) {
    int i = blockIdx.x * blockDim.x + threadIdx.x;
    if (i < n) out[i] = 0.f;
}

extern "C" void kernel_launch(void* const* d_in, const int* in_sizes, int n_in,
                              void* d_out, int out_size)
{
    const float* span   = (const float*)d_in[0];
    const int*   preds  = (const int*)d_in[1];
    const int*   labels = (const int*)d_in[2];
    // d_in[3] = len_info (dense case, unused)
    // FFNN bug: only the LAST layer (index FF-1 = 1) of each stack matters.
    const float* Wp  = (const float*)d_in[4] + (size_t)ND * ND;
    const float* bpv = (const float*)d_in[5] + ND;
    const float* Wa  = (const float*)d_in[6] + (size_t)ND * ND;
    const float* bav = (const float*)d_in[7] + ND;
    const float* wp  = (const float*)d_in[8];
    const float* wa  = (const float*)d_in[9];
    const float* W1  = (const float*)d_in[10];
    const float* W2  = (const float*)d_in[11];
    const float* bias = (const float*)d_in[12];
    float* out = (float*)d_out;

    float* scr = nullptr;
    cudaGetSymbolAddress((void**)&scr, g_scratch);
    float* pred = scr + OFF_PRED;
    float* hid  = scr + OFF_HID;
    float* psc  = scr + OFF_PSC;
    float* asc  = scr + OFF_ASC;
    float* p2   = scr + OFF_P2;
    float* s2   = scr + OFF_S2;
    float* U    = scr + OFF_U;

    // 1) gather predicate representations
    k_gather<<<BPD, 256>>>(span, preds, pred);

    // 2) unary scores (last FFNN layer only)
    k_gemm_nt_relu<<<dim3(ND / 128, BPD / 128), 256>>>(pred, Wp, bpv, hid);
    k_rowdot<<<BPD, 256>>>(hid, wp, psc);
    k_gemm_nt_relu<<<dim3(ND / 128, BSD / 128), 256>>>(span, Wa, bav, hid);
    k_rowdot<<<BSD, 256>>>(hid, wa, asc);

    // 3) concat-linear terms
    k_gemm_nn64<<<dim3(1, BPD / 64), 256>>>(pred, W2, p2);
    k_gemm_nn64<<<dim3(1, BSD / 64), 256>>>(span, W2 + (size_t)ND * NL, s2);

    // 4) bilinear stage 1: U = pred @ W1[l]  (batched over labels)
    k_gemm_u<<<dim3(ND / 128, BPD / 128, NL), 256>>>(pred, W1, U);

    // 5) bilinear stage 2 fused with full epilogue -> scores
    k_final<<<dim3(1, NS / 64, BPD), 256>>>(span, U, p2, s2, psc, asc, bias, out);

    // 6) outputs beyond the score matrix: real_labels (cast to output dtype)
    const int n_scores = NB * NP * NS * NL;   // 16777216
    const int n_lab = NB * NP * NS;           // 262144
    int written = n_scores;
    if (out_size >= n_scores + n_lab) {
        k_labels<<<(n_lab + 255) / 256, 256>>>(labels, out + n_scores, n_lab);
        written += n_lab;
    }
    if (out_size > written) {
        int rem = out_size - written;
        k_zero<<<(rem + 255) / 256, 256>>>(out + written, rem);
    }
}